// round 13
// baseline (speedup 1.0000x reference)
#include <cuda_runtime.h>

// LIF neuron scan, T=16:
//   u1 = mem*0.5 + x[t]*0.5 ; spike = (u1 > 1) ; mem = spike ? 0 : u1
//
// HBM-roofline streaming kernel (512 MB compulsory 1:1 R/W traffic,
// measured ceiling ~6.4 TB/s). R13 lever: Blackwell 256-bit global
// loads/stores (ld/st.global.v8.f32, PTX 8.7, sm_100+) — halves LDG/STG
// instruction count and L1tex wavefronts per byte vs float4.
//
// All other levers fixed at the measured optimum (R1-R12):
//   - 1 column per thread, interleaved t-loop, pointer-bump addressing
//   - default cache policy (beats .cs/.cg variants in 4 separate tests)
//   - exact grid, no guard, 32-bit thread indexing

#define TSTEPS 16

__global__ void __launch_bounds__(256)
lif_scan_kernel(const float* __restrict__ x, float* __restrict__ out)
{
    // 67,108,864 / 16 timesteps = 4,194,304 floats per step = 524,288 float8 cols.
    const unsigned col = blockIdx.x * 256u + threadIdx.x;        // 0 .. 2^19-1
    const unsigned stride = 1u << 22;                            // floats per timestep

    const float* xp = x + (size_t)col * 8u;
    float* op = out + (size_t)col * 8u;

    float m0 = 0.f, m1 = 0.f, m2 = 0.f, m3 = 0.f;
    float m4 = 0.f, m5 = 0.f, m6 = 0.f, m7 = 0.f;

    #pragma unroll
    for (int t = 0; t < TSTEPS; ++t) {
        float v0, v1, v2, v3, v4, v5, v6, v7;
        asm volatile(
            "ld.global.v8.f32 {%0, %1, %2, %3, %4, %5, %6, %7}, [%8];"
            : "=f"(v0), "=f"(v1), "=f"(v2), "=f"(v3),
              "=f"(v4), "=f"(v5), "=f"(v6), "=f"(v7)
            : "l"(xp));

        float u;
        u = fmaf(m0, 0.5f, v0 * 0.5f); v0 = (u > 1.f) ? 1.f : 0.f; m0 = (u > 1.f) ? 0.f : u;
        u = fmaf(m1, 0.5f, v1 * 0.5f); v1 = (u > 1.f) ? 1.f : 0.f; m1 = (u > 1.f) ? 0.f : u;
        u = fmaf(m2, 0.5f, v2 * 0.5f); v2 = (u > 1.f) ? 1.f : 0.f; m2 = (u > 1.f) ? 0.f : u;
        u = fmaf(m3, 0.5f, v3 * 0.5f); v3 = (u > 1.f) ? 1.f : 0.f; m3 = (u > 1.f) ? 0.f : u;
        u = fmaf(m4, 0.5f, v4 * 0.5f); v4 = (u > 1.f) ? 1.f : 0.f; m4 = (u > 1.f) ? 0.f : u;
        u = fmaf(m5, 0.5f, v5 * 0.5f); v5 = (u > 1.f) ? 1.f : 0.f; m5 = (u > 1.f) ? 0.f : u;
        u = fmaf(m6, 0.5f, v6 * 0.5f); v6 = (u > 1.f) ? 1.f : 0.f; m6 = (u > 1.f) ? 0.f : u;
        u = fmaf(m7, 0.5f, v7 * 0.5f); v7 = (u > 1.f) ? 1.f : 0.f; m7 = (u > 1.f) ? 0.f : u;

        asm volatile(
            "st.global.v8.f32 [%0], {%1, %2, %3, %4, %5, %6, %7, %8};"
            :: "l"(op),
               "f"(v0), "f"(v1), "f"(v2), "f"(v3),
               "f"(v4), "f"(v5), "f"(v6), "f"(v7)
            : "memory");

        xp += stride;
        op += stride;
    }
}

extern "C" void kernel_launch(void* const* d_in, const int* in_sizes, int n_in,
                              void* d_out, int out_size)
{
    const float* x = (const float*)d_in[0];
    float* out = (float*)d_out;

    // 524,288 float8 columns / 256 threads = 2048 CTAs exactly.
    lif_scan_kernel<<<2048, 256>>>(x, out);
}

// round 14
// speedup vs baseline: 1.0209x; 1.0209x over previous
#include <cuda_runtime.h>

// LIF neuron scan, T=16:
//   u1 = mem*0.5 + x[t]*0.5 ; spike = (u1 > 1) ; mem = spike ? 0 : u1
//
// FINAL KERNEL — HBM-roofline streaming. 512 MB compulsory 1:1 R/W traffic
// at ~6.4 TB/s (80-81% of 8 TB/s spec), the measured B300 mixed-stream
// ceiling. 13-round lever matrix, all isolated:
//   - per-thread MLP: 1 float4 column best (16-batch neutral R2,
//     2-col + occ collapse fatal R3)
//   - cache policy: default beats .cs-both/.cs-ld/.cs-st/.cg-ld
//     (R2/R6/R9/R10)
//   - access width: 256-bit v8 ops neutral (R13) — DRAM cap path-independent
//   - block size 128/256/512 equivalent (R5/R12); wave tail irrelevant (R5)
//   - 32-bit pointer-bump addressing (R7), exact grid, no guard
// Best profile: 6434 GB/s, DRAM 81.2%, ncu 75.4 us (R8 config = this one).

#define TSTEPS 16

__global__ void __launch_bounds__(512)
lif_scan_kernel(const float* __restrict__ x, float* __restrict__ out)
{
    const unsigned col = blockIdx.x * 512u + threadIdx.x;   // 0 .. 2^20-1
    const unsigned stride4 = 1u << 20;                      // float4 cols per timestep

    const float4* __restrict__ xp = reinterpret_cast<const float4*>(x) + col;
    float4* __restrict__ op = reinterpret_cast<float4*>(out) + col;

    float4 mem = make_float4(0.f, 0.f, 0.f, 0.f);

    #pragma unroll
    for (int t = 0; t < TSTEPS; ++t) {
        const float4 xt = *xp;

        float4 s;
        float u;
        u = fmaf(mem.x, 0.5f, xt.x * 0.5f); s.x = (u > 1.f) ? 1.f : 0.f; mem.x = (u > 1.f) ? 0.f : u;
        u = fmaf(mem.y, 0.5f, xt.y * 0.5f); s.y = (u > 1.f) ? 1.f : 0.f; mem.y = (u > 1.f) ? 0.f : u;
        u = fmaf(mem.z, 0.5f, xt.z * 0.5f); s.z = (u > 1.f) ? 1.f : 0.f; mem.z = (u > 1.f) ? 0.f : u;
        u = fmaf(mem.w, 0.5f, xt.w * 0.5f); s.w = (u > 1.f) ? 1.f : 0.f; mem.w = (u > 1.f) ? 0.f : u;

        *op = s;

        xp += stride4;   // single IADD per pointer per step
        op += stride4;
    }
}

extern "C" void kernel_launch(void* const* d_in, const int* in_sizes, int n_in,
                              void* d_out, int out_size)
{
    const float* x = (const float*)d_in[0];
    float* out = (float*)d_out;

    // 67,108,864 elements / 16 timesteps / 4 per float4 / 512 threads = 2048 CTAs exactly.
    lif_scan_kernel<<<2048, 512>>>(x, out);
}